// round 5
// baseline (speedup 1.0000x reference)
#include <cuda_runtime.h>

#define NEG_INF  (-1e8f)
#define M_EMPTY  (-1e30f)
#define INVLN2 1.4426950408889634f
#define LN2    0.6931471805599453f

__device__ __forceinline__ float ex2f(float x){ float r; asm("ex2.approx.ftz.f32 %0, %1;" : "=f"(r) : "f"(x)); return r; }
__device__ __forceinline__ float lg2f(float x){ float r; asm("lg2.approx.ftz.f32 %0, %1;" : "=f"(r) : "f"(x)); return r; }

// log2-domain logsumexp
__device__ __forceinline__ float lse2(float a, float b){
    float m = fmaxf(a, b);
    return m + lg2f(1.0f + ex2f(-fabsf(a - b)));
}
__device__ __forceinline__ float lse3(float a, float b, float c){
    float m = fmaxf(fmaxf(a, b), c);
    return m + lg2f(ex2f(a - m) + ex2f(b - m) + ex2f(c - m));
}
// online-softmax pair fold: (M,Q) += (Ma,Qa); represents log2 Sum = M + lg2(Q)
__device__ __forceinline__ void mqcomb(float& M, float& Q, float Ma, float Qa){
    float Mx = fmaxf(M, Ma);
    float f  = ex2f(-fabsf(M - Ma));
    Q = (M >= Ma) ? fmaf(Qa, f, Q) : fmaf(Q, f, Qa);
    M = Mx;
}

// One CTA (128 threads, 4 warps) per batch. Thread t owns grid columns 2t, 2t+1.
// Per row:  u0 = th0 + LSE3(Vdiag + A[0,:]),  u1 = th1 + LSE3(Vup + A[1,:])
//           x_j = LSE(c_j, a_j + x_{j-1}),  c_j = th2 + LSE2(u0_{j-1}+A6, u1_{j-1}+A7),
//           a_j = th2 + A8.
// Scan factorization:  x_j = S_j + log2 Sum_{k<=j} 2^{T_k},  S_j = prefix-sum(a),
// T_k = c_k - S_k.  Prefix-LSE of T via (M,Q) online-softmax Kogge-Stone.
__global__ __launch_bounds__(128, 1)
void forward_decoder_kernel(const float* __restrict__ theta,
                            const float* __restrict__ A,
                            float* __restrict__ out){
    constexpr int N = 256;
    const int t    = threadIdx.x;     // 0..127
    const int lane = t & 31;
    const int wg   = t >> 5;          // warp 0..3
    const int b    = blockIdx.x;

    __shared__ float sU0[128], sU1[128];
    __shared__ float sMA[2][4], sQA[2][4], sSA[2][4];  // double-buffered per row parity

    const float* thb = theta + (size_t)b * 256 * 256 * 3;
    const float* Ab  = A     + (size_t)b * 256 * 256 * 9;

    // prefetch row 0: 3+9 float2 loads (8B aligned, warp spans contiguous 3KB)
    float2 p[12];
    {
        const float2* tp = (const float2*)(thb + 6 * (size_t)t);
        const float2* ap = (const float2*)(Ab + 18 * (size_t)t);
        p[0]=__ldg(tp); p[1]=__ldg(tp+1); p[2]=__ldg(tp+2);
        #pragma unroll
        for(int k = 0; k < 9; k++) p[3+k] = __ldg(ap + k);
    }

    float pv0e=NEG_INF, pv1e=NEG_INF, pv2e=NEG_INF;   // prev-row V at even col 2t
    float pv0o=NEG_INF, pv1o=NEG_INF, pv2o=NEG_INF;   // prev-row V at odd col 2t+1
    float dn0 =NEG_INF, dn1 =NEG_INF, dn2 =NEG_INF;   // prev-row V at col 2t-1

    for(int i = 0; i < N; i++){
        const int ib = i & 1;
        // consume prefetched row (scale to log2 domain)
        float t0e=p[0].x*INVLN2, t1e=p[0].y*INVLN2, t2e=p[1].x*INVLN2;
        float t0o=p[1].y*INVLN2, t1o=p[2].x*INVLN2, t2o=p[2].y*INVLN2;
        float e0=p[3].x*INVLN2,  e1=p[3].y*INVLN2,  e2=p[4].x*INVLN2;
        float e3=p[4].y*INVLN2,  e4=p[5].x*INVLN2,  e5=p[5].y*INVLN2;
        float e6=p[6].x*INVLN2,  e7=p[6].y*INVLN2,  e8=p[7].x*INVLN2;
        float o0=p[7].y*INVLN2,  o1=p[8].x*INVLN2,  o2=p[8].y*INVLN2;
        float o3=p[9].x*INVLN2,  o4=p[9].y*INVLN2,  o5=p[10].x*INVLN2;
        float o6=p[10].y*INVLN2, o7=p[11].x*INVLN2, o8=p[11].y*INVLN2;

        // issue next row's loads (hide DRAM under this row's compute)
        if(i + 1 < N){
            const float2* tp = (const float2*)(thb + (size_t)(i+1)*768  + 6  * (size_t)t);
            const float2* ap = (const float2*)(Ab  + (size_t)(i+1)*2304 + 18 * (size_t)t);
            p[0]=__ldg(tp); p[1]=__ldg(tp+1); p[2]=__ldg(tp+2);
            #pragma unroll
            for(int k = 0; k < 9; k++) p[3+k] = __ldg(ap + k);
        }

        // diagonal for even column = prev-row V at col 2t-1
        float d0, d1, d2;
        if(t == 0){ float bv = (i == 0) ? 0.0f : NEG_INF; d0=bv; d1=bv; d2=bv; }
        else      { d0=dn0; d1=dn1; d2=dn2; }

        float u0e  = t0e + lse3(d0  + e0, d1  + e1, d2  + e2);
        float u1e  = t1e + lse3(pv0e + e3, pv1e + e4, pv2e + e5);
        float nu0o = t0o + lse3(pv0e + o0, pv1e + o1, pv2e + o2);
        float nu1o = t1o + lse3(pv0o + o3, pv1o + o4, pv2o + o5);

        // cheap FADD prefix-sum of a over lanes (local to warp); overlaps lse3s
        float a_e = t2e + e8, a_o = t2o + o8;
        float Sin = a_e + a_o;
        #pragma unroll
        for(int dlt = 1; dlt < 32; dlt <<= 1){
            float v = __shfl_up_sync(0xffffffffu, Sin, dlt);
            if(lane >= dlt) Sin += v;
        }

        sU0[t] = nu0o; sU1[t] = nu1o;
        if(lane == 31) sSA[ib][wg] = Sin;
        __syncthreads();                       // bar A: u exchange + S aggregates

        float num0 = t ? sU0[t-1] : NEG_INF;
        float num1 = t ? sU1[t-1] : NEG_INF;

        float c_e = t2e + lse2(num0 + e6, num1 + e7);   // col 2t
        float c_o = t2o + lse2(u0e  + o6, u1e  + o7);   // col 2t+1

        // warp-local frame T' = c - S_local (uniform Swpre shift fixed after bar B)
        float Sl_o = Sin;
        float Sl_e = Sin - a_o;
        float Te = c_e - Sl_e;
        float To = c_o - Sl_o;

        // thread element: 2^Te + 2^To as (M,Q)
        float Mi = fmaxf(Te, To);
        float Qi = 1.0f + ex2f(-fabsf(Te - To));

        // intra-warp inclusive (M,Q) Kogge-Stone: 1 ex2 + 1 FMA per step
        #pragma unroll
        for(int dlt = 1; dlt < 32; dlt <<= 1){
            float Mn = __shfl_up_sync(0xffffffffu, Mi, dlt);
            float Qn = __shfl_up_sync(0xffffffffu, Qi, dlt);
            float Mx = fmaxf(Mi, Mn);
            float f  = ex2f(-fabsf(Mi - Mn));
            float Qx = (Mi >= Mn) ? fmaf(Qn, f, Qi) : fmaf(Qi, f, Qn);
            if(lane >= dlt){ Mi = Mx; Qi = Qx; }
        }
        // lane-exclusive
        float eM = __shfl_up_sync(0xffffffffu, Mi, 1);
        float eQ = __shfl_up_sync(0xffffffffu, Qi, 1);
        if(lane == 0){ eM = M_EMPTY; eQ = 0.0f; }

        if(lane == 31){ sMA[ib][wg] = Mi; sQA[ib][wg] = Qi; }
        __syncthreads();                       // bar B: warp aggregates ready

        // unordered fold of aggregates from warps < wg, shifting each into the
        // true frame (M_true = M_local - Swpre_of_that_warp)
        float Mp = M_EMPTY, Qp = 0.0f, run = 0.0f;
        #pragma unroll
        for(int v = 0; v < 3; v++){
            float Ma = sMA[ib][v] - run;
            float Qa = sQA[ib][v];
            float Mx = fmaxf(Mp, Ma);
            float f  = ex2f(-fabsf(Mp - Ma));
            float Qx = (Mp >= Ma) ? fmaf(Qa, f, Qp) : fmaf(Qp, f, Qa);
            float rn = run + sSA[ib][v];
            if(v < wg){ Mp = Mx; Qp = Qx; run = rn; }
        }
        float Swpre = run;
        float S_o = Swpre + Sl_o;              // true inclusive S at odd col
        float S_e = S_o - a_o;                 // true inclusive S at even col

        // P at col 2t-1 (lane-exclusive): dn2 for next row's diagonal
        float M1 = Mp, Q1 = Qp;
        mqcomb(M1, Q1, eM - Swpre, eQ);
        float dn2n = (S_e - a_e) + M1 + lg2f(Q1);

        // x at even col: add own T_e element
        float M2 = M1, Q2 = Q1;
        mqcomb(M2, Q2, Te - Swpre, 1.0f);
        float x_e = S_e + M2 + lg2f(Q2);

        // x at odd col: warp prefix + lane-inclusive
        float M3 = Mp, Q3 = Qp;
        mqcomb(M3, Q3, Mi - Swpre, Qi);
        float x_o = S_o + M3 + lg2f(Q3);

        pv0e = u0e;  pv1e = u1e;  pv2e = x_e;
        pv0o = nu0o; pv1o = nu1o; pv2o = x_o;
        dn0  = num0; dn1  = num1; dn2  = dn2n;
    }

    // terminal logsumexp at grid cell (N, M) = odd column of t=127
    if(t == 127) out[b] = LN2 * lse3(pv0o, pv1o, pv2o);
}

extern "C" void kernel_launch(void* const* d_in, const int* in_sizes, int n_in,
                              void* d_out, int out_size) {
    const float* theta = (const float*)d_in[0];
    const float* A     = (const float*)d_in[1];
    // d_in[2] = pos: fixed [(-1,-1),(-1,0),(0,-1)] -> (diag, up, left), hard-coded.
    float* out = (float*)d_out;
    int B = out_size;                 // 128 batches, one CTA each (all SMs busy)
    forward_decoder_kernel<<<B, 128>>>(theta, A, out);
}